// round 1
// baseline (speedup 1.0000x reference)
#include <cuda_runtime.h>

// ForwardWarp: forward splatting with Gaussian softmax weights.
// img, counts: (8,1,720,1280) f32; flo: (8,2,720,1280) f32 (ch0 = y shifts W, ch1 = x shifts H)
// out: [0:S) = img_warp / (one_warp + eps), [S:2S) = one_warp

static constexpr int N_ = 8;
static constexpr int H_ = 720;
static constexpr int W_ = 1280;
static constexpr int S_ = N_ * H_ * W_;   // 7,372,800
static constexpr float EPS_ = 1e-6f;

__global__ void __launch_bounds__(256) splat_kernel(
    const float* __restrict__ img,
    const float* __restrict__ counts,
    const float* __restrict__ flo,
    float* __restrict__ acc)   // acc[0:S) img-weighted, acc[S:2S) ones-weighted
{
    int idx = blockIdx.x * blockDim.x + threadIdx.x;
    if (idx >= S_) return;

    int w  = idx % W_;
    int hw = idx / W_;
    int h  = hw % H_;
    int n  = hw / H_;

    // flo layout: (N, 2, H, W). channel 0 = y (shifts W axis), channel 1 = x (shifts H axis)
    int flo_base = ((n * 2) * H_ + h) * W_ + w;
    float y = flo[flo_base];
    float x = flo[flo_base + H_ * W_];

    float im = img[idx];
    float c  = counts[idx];

    float x1 = floorf(x);
    float y1 = floorf(y);
    float fx = x - x1;            // (x - x1)
    float fy = y - y1;
    float gx = fx - 1.0f;         // (x - x2)
    float gy = fy - 1.0f;

    float dx1 = fx * fx, dx2 = gx * gx;
    float dy1 = fy * fy, dy2 = gy * gy;

    float w11 = __expf(-(dx1 + dy1));
    float w12 = __expf(-(dx1 + dy2));
    float w21 = __expf(-(dx2 + dy1));
    float w22 = __expf(-(dx2 + dy2));
    float inv = 1.0f / (w11 + w12 + w21 + w22);
    w11 *= inv; w12 *= inv; w21 *= inv; w22 *= inv;

    int ix1 = (int)x1 + h;
    int ix2 = ix1 + 1;
    int iy1 = (int)y1 + w;
    int iy2 = iy1 + 1;

    float cw;
    float* __restrict__ acc_img = acc;
    float* __restrict__ acc_one = acc + S_;
    int nb = n * H_;

    // tap (x1, y1) -> w11
    if (ix1 >= 0 && ix1 < H_ && iy1 >= 0 && iy1 < W_) {
        int q = (nb + ix1) * W_ + iy1;
        cw = c * w11;
        atomicAdd(acc_img + q, im * cw);
        atomicAdd(acc_one + q, cw);
    }
    // tap (x1, y2) -> w12
    if (ix1 >= 0 && ix1 < H_ && iy2 >= 0 && iy2 < W_) {
        int q = (nb + ix1) * W_ + iy2;
        cw = c * w12;
        atomicAdd(acc_img + q, im * cw);
        atomicAdd(acc_one + q, cw);
    }
    // tap (x2, y1) -> w21
    if (ix2 >= 0 && ix2 < H_ && iy1 >= 0 && iy1 < W_) {
        int q = (nb + ix2) * W_ + iy1;
        cw = c * w21;
        atomicAdd(acc_img + q, im * cw);
        atomicAdd(acc_one + q, cw);
    }
    // tap (x2, y2) -> w22
    if (ix2 >= 0 && ix2 < H_ && iy2 >= 0 && iy2 < W_) {
        int q = (nb + ix2) * W_ + iy2;
        cw = c * w22;
        atomicAdd(acc_img + q, im * cw);
        atomicAdd(acc_one + q, cw);
    }
}

__global__ void __launch_bounds__(256) normalize_kernel(float* __restrict__ out)
{
    int i = blockIdx.x * blockDim.x + threadIdx.x;
    if (i >= S_) return;
    out[i] = out[i] / (out[S_ + i] + EPS_);
}

extern "C" void kernel_launch(void* const* d_in, const int* in_sizes, int n_in,
                              void* d_out, int out_size)
{
    const float* img    = (const float*)d_in[0];
    const float* counts = (const float*)d_in[1];
    const float* flo    = (const float*)d_in[2];
    float* out = (float*)d_out;

    // zero both accumulator halves (d_out is poisoned)
    cudaMemsetAsync(out, 0, (size_t)2 * S_ * sizeof(float));

    int threads = 256;
    int blocks = (S_ + threads - 1) / threads;
    splat_kernel<<<blocks, threads>>>(img, counts, flo, out);
    normalize_kernel<<<blocks, threads>>>(out);
}

// round 2
// speedup vs baseline: 1.9539x; 1.9539x over previous
#include <cuda_runtime.h>

// ForwardWarp: forward splatting with Gaussian softmax weights.
// img, counts: (8,1,720,1280) f32; flo: (8,2,720,1280) f32 (ch0 = y shifts W axis, ch1 = x shifts H axis)
// out: [0:S) = img_warp / (one_warp + eps), [S:2S) = one_warp
//
// Strategy: accumulate into interleaved [img, one] pairs in device scratch so each
// tap is ONE red.global.add.v2.f32; fuse the two adjacent-column taps of a row into
// a single red.global.add.v4.f32 when 16B-aligned. Splat is REDG-issue bound, so
// fewer/wider RED instructions == proportional speedup.

static constexpr int N_ = 8;
static constexpr int H_ = 720;
static constexpr int W_ = 1280;
static constexpr int S_ = N_ * H_ * W_;   // 7,372,800
static constexpr float EPS_ = 1e-6f;

// Interleaved accumulator: pair p = { img_weighted, one_weighted } at g_acc[2p], g_acc[2p+1]
__device__ float g_acc[2 * S_];

__device__ __forceinline__ void red_v2(float* p, float a, float b) {
    asm volatile("red.global.add.v2.f32 [%0], {%1, %2};"
                 :: "l"(p), "f"(a), "f"(b) : "memory");
}
__device__ __forceinline__ void red_v4(float* p, float a, float b, float c, float d) {
    asm volatile("red.global.add.v4.f32 [%0], {%1, %2, %3, %4};"
                 :: "l"(p), "f"(a), "f"(b), "f"(c), "f"(d) : "memory");
}

__global__ void __launch_bounds__(256) splat_kernel(
    const float* __restrict__ img,
    const float* __restrict__ counts,
    const float* __restrict__ flo)
{
    int idx = blockIdx.x * blockDim.x + threadIdx.x;
    if (idx >= S_) return;

    int w  = idx % W_;
    int hw = idx / W_;
    int h  = hw % H_;
    int n  = hw / H_;

    // flo layout: (N, 2, H, W). channel 0 = y (shifts W axis), channel 1 = x (shifts H axis)
    int flo_base = ((n * 2) * H_ + h) * W_ + w;
    float y = flo[flo_base];
    float x = flo[flo_base + H_ * W_];

    float im = img[idx];
    float c  = counts[idx];

    float x1 = floorf(x);
    float y1 = floorf(y);
    float fx = x - x1;            // (x - x1) in [0,1)
    float fy = y - y1;
    float gx = fx - 1.0f;         // (x - x2)
    float gy = fy - 1.0f;

    float dx1 = fx * fx, dx2 = gx * gx;
    float dy1 = fy * fy, dy2 = gy * gy;

    float w11 = __expf(-(dx1 + dy1));
    float w12 = __expf(-(dx1 + dy2));
    float w21 = __expf(-(dx2 + dy1));
    float w22 = __expf(-(dx2 + dy2));
    float inv = 1.0f / (w11 + w12 + w21 + w22);

    // counts-scaled weights; a = column y1, b = column y2
    float cinv = c * inv;
    float wa1 = w11 * cinv, wb1 = w12 * cinv;   // row x1
    float wa2 = w21 * cinv, wb2 = w22 * cinv;   // row x2

    int ix1 = (int)x1 + h;
    int ix2 = ix1 + 1;
    int iy1 = (int)y1 + w;
    int iy2 = iy1 + 1;

    bool va = (iy1 >= 0) & (iy1 < W_);
    bool vb = (iy2 >= 0) & (iy2 < W_);
    if (!(va | vb)) return;

    int nb = n * H_;
    bool aligned = ((iy1 & 1) == 0);

    // row 1: taps (ix1, iy1)*wa1, (ix1, iy2)*wb1
    if (ix1 >= 0 && ix1 < H_) {
        int p = (nb + ix1) * W_ + iy1;      // pair index of column iy1
        float* base = g_acc + 2 * p;
        if (va & vb) {
            if (aligned) red_v4(base, im * wa1, wa1, im * wb1, wb1);
            else { red_v2(base, im * wa1, wa1); red_v2(base + 2, im * wb1, wb1); }
        } else if (va) {
            red_v2(base, im * wa1, wa1);
        } else {
            red_v2(base + 2, im * wb1, wb1);
        }
    }
    // row 2: taps (ix2, iy1)*wa2, (ix2, iy2)*wb2
    if (ix2 >= 0 && ix2 < H_) {
        int p = (nb + ix2) * W_ + iy1;
        float* base = g_acc + 2 * p;
        if (va & vb) {
            if (aligned) red_v4(base, im * wa2, wa2, im * wb2, wb2);
            else { red_v2(base, im * wa2, wa2); red_v2(base + 2, im * wb2, wb2); }
        } else if (va) {
            red_v2(base, im * wa2, wa2);
        } else {
            red_v2(base + 2, im * wb2, wb2);
        }
    }
}

// Each thread handles 2 pairs (one float4 of scratch) -> 2 outputs in each half.
__global__ void __launch_bounds__(256) normalize_kernel(float* __restrict__ out)
{
    int t = blockIdx.x * blockDim.x + threadIdx.x;
    if (t >= S_ / 2) return;
    float4 v = reinterpret_cast<const float4*>(g_acc)[t];   // pairs 2t, 2t+1
    float2 o0, o1;
    o0.x = v.x / (v.y + EPS_);
    o0.y = v.z / (v.w + EPS_);
    o1.x = v.y;
    o1.y = v.w;
    reinterpret_cast<float2*>(out)[t] = o0;
    reinterpret_cast<float2*>(out + S_)[t] = o1;
}

extern "C" void kernel_launch(void* const* d_in, const int* in_sizes, int n_in,
                              void* d_out, int out_size)
{
    const float* img    = (const float*)d_in[0];
    const float* counts = (const float*)d_in[1];
    const float* flo    = (const float*)d_in[2];
    float* out = (float*)d_out;

    void* acc_ptr = nullptr;
    cudaGetSymbolAddress(&acc_ptr, g_acc);
    cudaMemsetAsync(acc_ptr, 0, (size_t)2 * S_ * sizeof(float));

    int threads = 256;
    int blocks = (S_ + threads - 1) / threads;
    splat_kernel<<<blocks, threads>>>(img, counts, flo);
    normalize_kernel<<<(S_ / 2 + threads - 1) / threads, threads>>>(out);
}